// round 3
// baseline (speedup 1.0000x reference)
#include <cuda_runtime.h>
#include <cuda_bf16.h>
#include <cstdint>

#define DIMN 512
#define MT   64
#define NROWS 65536
#define NCTAS (NROWS / MT)        // 1024
#define NTHREADS 512
#define ETA   0.1f
#define OMETA 0.9f

// smem: a-tile [64][512] bf16 swizzled (64KB) + 4 G k-slice buffers [32][512] bf16 (32KB each) + flags
static constexpr uint32_t A_OFF   = 0;
static constexpr uint32_t G_OFF   = 65536;        // + s*32768, s=0..3
static constexpr uint32_t FL_OFF  = 196608;       // flags[2][16] uint32 = 128B
static constexpr uint32_t SMEM_TOTAL = 196736;

#define NCHUNKS_TOTAL (9 * 16)    // 144

// G' = -eta * (0.5*(G+G^T)) with zero diagonal, bf16, row-major [K=512][N=512]
__device__ __nv_bfloat16 g_gp[DIMN * DIMN];

__global__ void lca_prep_kernel(const float* __restrict__ G) {
    int idx = blockIdx.x * blockDim.x + threadIdx.x;
    int i = idx >> 9, j = idx & 511;
    float v = (i == j) ? 0.0f : -ETA * 0.5f * (G[idx] + G[j * DIMN + i]);
    g_gp[idx] = __float2bfloat16(v);
}

__device__ __forceinline__ uint32_t smem_u32(const void* p) {
    uint32_t a;
    asm("{ .reg .u64 t; cvta.to.shared.u64 t, %1; cvt.u32.u64 %0, t; }" : "=r"(a) : "l"(p));
    return a;
}
__device__ __forceinline__ void ldsm4(uint32_t* r, uint32_t addr) {
    asm volatile("ldmatrix.sync.aligned.m8n8.x4.shared.b16 {%0,%1,%2,%3}, [%4];"
                 : "=r"(r[0]), "=r"(r[1]), "=r"(r[2]), "=r"(r[3]) : "r"(addr));
}
__device__ __forceinline__ void ldsm4t(uint32_t* r, uint32_t addr) {
    asm volatile("ldmatrix.sync.aligned.m8n8.x4.trans.shared.b16 {%0,%1,%2,%3}, [%4];"
                 : "=r"(r[0]), "=r"(r[1]), "=r"(r[2]), "=r"(r[3]) : "r"(addr));
}
__device__ __forceinline__ void mma_bf16(float* c, const uint32_t* a, uint32_t b0, uint32_t b1) {
    asm volatile("mma.sync.aligned.m16n8k16.row.col.f32.bf16.bf16.f32 "
                 "{%0,%1,%2,%3}, {%4,%5,%6,%7}, {%8,%9}, {%0,%1,%2,%3};"
                 : "+f"(c[0]), "+f"(c[1]), "+f"(c[2]), "+f"(c[3])
                 : "r"(a[0]), "r"(a[1]), "r"(a[2]), "r"(a[3]), "r"(b0), "r"(b1));
}
__device__ __forceinline__ void cp_async16(uint32_t dst, const void* src) {
    asm volatile("cp.async.cg.shared.global [%0], [%1], 16;" :: "r"(dst), "l"(src) : "memory");
}

// load G chunk rb (rows rb*32..+32, [32][512] bf16 = 32KB) into SMEM buffer at boff
__device__ __forceinline__ void load_chunk(uint32_t sb, uint32_t boff, int rb, int tid) {
    const char* src = (const char*)g_gp + (size_t)rb * 32768 + (size_t)tid * 16;
#pragma unroll
    for (int j = 0; j < 4; j++) {
        int q = tid + j * 512;
        int r = q >> 6, cu = q & 63;
        uint32_t dst = sb + boff + (uint32_t)r * 1024u + ((uint32_t)(cu ^ (r & 7)) << 4);
        cp_async16(dst, src + j * 8192);
    }
    asm volatile("cp.async.commit_group;" ::: "memory");
}

__global__ __launch_bounds__(NTHREADS, 1)
void lca_main_kernel(const float* __restrict__ u,
                     const float* __restrict__ log_lam,
                     float* __restrict__ out) {
    extern __shared__ char smem[];
    const uint32_t sb = smem_u32(smem);
    uint32_t* flagsm = reinterpret_cast<uint32_t*>(smem + FL_OFF);   // [2][16]
    const int tid  = threadIdx.x;
    const int lane = tid & 31;
    const int warp = tid >> 5;
    const int wm = warp >> 3;              // 0..1  (32-row half)
    const int wn = warp & 7;               // 0..7  (64-col group)
    const int m0 = wm * 32;
    const int n0 = wn * 64;
    const uint32_t un0 = (uint32_t)(n0 >> 3);
    const int grow0 = blockIdx.x * MT;
    const float lam = expf(log_lam[0]);
    const int r4 = lane >> 2;
    const int c2 = (lane & 3) * 2;

    float acc[2][8][4];

    // ldmatrix lane-constant addresses
    const uint32_t a_lrow0 = sb + A_OFF + (uint32_t)(m0 + (lane & 15)) * 1024u;
    const uint32_t a_lrow1 = a_lrow0 + 16u * 1024u;
    const uint32_t a_cbs = ((uint32_t)(lane >> 4)) ^ ((uint32_t)(lane & 7));
    const uint32_t b_rowoff = (uint32_t)(lane & 15) * 1024u;
    uint32_t b_pu[4];
#pragma unroll
    for (int p = 0; p < 4; p++)
        b_pu[p] = (((un0 + (uint32_t)(2 * p) + (uint32_t)(lane >> 4)) ^ (uint32_t)(lane & 7)) << 4);

    // zero both flag slots; prefetch chunks 0,1 (distance-2 pipeline)
    if (tid < 32) flagsm[tid] = 0u;
    load_chunk(sb, G_OFF + 0 * 32768, 0, tid);
    load_chunk(sb, G_OFF + 1 * 32768, 1, tid);
    __syncthreads();   // flags zeroed before init epilogue's atomicOr

    // ---- init: v1 = eta*u; a1 = soft(v1) -> SMEM + flags slot 0; acc = 0.9*v1 + 0.1*u ----
    {
        bool nzlo = false, nzhi = false;
#pragma unroll
        for (int fm = 0; fm < 2; fm++)
#pragma unroll
        for (int rh = 0; rh < 2; rh++) {
            int rl = m0 + fm * 16 + rh * 8 + r4;
            const float* urow = u + (size_t)(grow0 + rl) * DIMN;
            uint32_t abase = sb + A_OFF + (uint32_t)rl * 1024u + (uint32_t)(c2 * 2);
            uint32_t sw = (uint32_t)(rl & 7);
#pragma unroll
            for (int ni = 0; ni < 8; ni++) {
                float2 uv = *(const float2*)(urow + n0 + ni * 8 + c2);
                float v0 = ETA * uv.x, v1 = ETA * uv.y;
                float s0 = fabsf(v0) - lam, s1 = fabsf(v1) - lam;
                float a0 = (s0 > 0.0f) ? copysignf(s0, v0) : 0.0f;
                float a1 = (s1 > 0.0f) ? copysignf(s1, v1) : 0.0f;
                bool nz = (a0 != 0.0f) || (a1 != 0.0f);
                if (ni < 4) nzlo |= nz; else nzhi |= nz;
                __nv_bfloat162 h2 = __floats2bfloat162_rn(a0, a1);
                uint32_t aaddr = abase + (((un0 + (uint32_t)ni) ^ sw) << 4);
                asm volatile("st.shared.b32 [%0], %1;" :: "r"(aaddr), "r"(*(uint32_t*)&h2) : "memory");
                acc[fm][ni][rh * 2 + 0] = fmaf(OMETA, v0, ETA * uv.x);
                acc[fm][ni][rh * 2 + 1] = fmaf(OMETA, v1, ETA * uv.y);
            }
        }
        bool wlo = __any_sync(0xFFFFFFFFu, nzlo);
        bool whi = __any_sync(0xFFFFFFFFu, nzhi);
        if (lane == 0) {
            if (wlo) atomicOr(&flagsm[2 * wn + 0], 1u);
            if (whi) atomicOr(&flagsm[2 * wn + 1], 1u);
        }
    }
    __syncthreads();

    // ---- 9 fused iterations ----
#pragma unroll 1
    for (int it = 0; it < 9; it++) {
        const int slot = it & 1;
#pragma unroll 1
        for (int kb = 0; kb < 16; kb++) {
            const int c = it * 16 + kb;
            // prefetch chunk c+2 into buffer (c+2)&3 (overwrites buffer last read at chunk c-2:
            // safe — all threads passed chunk c-1's barrier, which postdates all MMA(c-2))
            if (c + 2 < NCHUNKS_TOTAL) {
                load_chunk(sb, G_OFF + (uint32_t)((c + 2) & 3) * 32768u, (kb + 2) & 15, tid);
                asm volatile("cp.async.wait_group 2;" ::: "memory");
            } else {
                asm volatile("cp.async.wait_group 0;" ::: "memory");
            }
            __syncthreads();   // all threads' group for chunk c complete; prev MMA drained
            if (kb == 0 && tid < 16) flagsm[((it + 1) & 1) * 16 + tid] = 0u;  // clear next slot

            if (flagsm[slot * 16 + kb]) {
                const uint32_t buf = sb + G_OFF + (uint32_t)(c & 3) * 32768u;
#pragma unroll
                for (int h = 0; h < 2; h++) {
                    const int K = kb * 2 + h;
                    uint32_t A0[4], A1[4];
                    uint32_t aoff = (((uint32_t)(K << 1) ^ a_cbs) << 4);
                    ldsm4(A0, a_lrow0 + aoff);
                    ldsm4(A1, a_lrow1 + aoff);
                    uint32_t brow = buf + b_rowoff + (uint32_t)(h * 16384);
                    uint32_t B[4][4];
#pragma unroll
                    for (int p = 0; p < 4; p++) ldsm4t(B[p], brow + b_pu[p]);
#pragma unroll
                    for (int p = 0; p < 4; p++) {
                        mma_bf16(acc[0][2 * p + 0], A0, B[p][0], B[p][1]);
                        mma_bf16(acc[0][2 * p + 1], A0, B[p][2], B[p][3]);
                        mma_bf16(acc[1][2 * p + 0], A1, B[p][0], B[p][1]);
                        mma_bf16(acc[1][2 * p + 1], A1, B[p][2], B[p][3]);
                    }
                }
            }
        }
        __syncthreads();   // all MMAs of this iteration done before A-tile is rewritten

        if (it < 8) {
            bool nzlo = false, nzhi = false;
            const int wslot = (it + 1) & 1;
#pragma unroll
            for (int fm = 0; fm < 2; fm++)
#pragma unroll
            for (int rh = 0; rh < 2; rh++) {
                int rl = m0 + fm * 16 + rh * 8 + r4;
                const float* urow = u + (size_t)(grow0 + rl) * DIMN;
                uint32_t abase = sb + A_OFF + (uint32_t)rl * 1024u + (uint32_t)(c2 * 2);
                uint32_t sw = (uint32_t)(rl & 7);
#pragma unroll
                for (int ni = 0; ni < 8; ni++) {
                    float v0 = acc[fm][ni][rh * 2 + 0];
                    float v1 = acc[fm][ni][rh * 2 + 1];
                    float s0 = fabsf(v0) - lam, s1 = fabsf(v1) - lam;
                    float a0 = (s0 > 0.0f) ? copysignf(s0, v0) : 0.0f;
                    float a1 = (s1 > 0.0f) ? copysignf(s1, v1) : 0.0f;
                    bool nz = (a0 != 0.0f) || (a1 != 0.0f);
                    if (ni < 4) nzlo |= nz; else nzhi |= nz;
                    __nv_bfloat162 h2 = __floats2bfloat162_rn(a0, a1);
                    uint32_t aaddr = abase + (((un0 + (uint32_t)ni) ^ sw) << 4);
                    asm volatile("st.shared.b32 [%0], %1;" :: "r"(aaddr), "r"(*(uint32_t*)&h2) : "memory");
                    float2 uv = *(const float2*)(urow + n0 + ni * 8 + c2);
                    acc[fm][ni][rh * 2 + 0] = fmaf(OMETA, v0, ETA * uv.x);
                    acc[fm][ni][rh * 2 + 1] = fmaf(OMETA, v1, ETA * uv.y);
                }
            }
            bool wlo = __any_sync(0xFFFFFFFFu, nzlo);
            bool whi = __any_sync(0xFFFFFFFFu, nzhi);
            if (lane == 0) {
                if (wlo) atomicOr(&flagsm[wslot * 16 + 2 * wn + 0], 1u);
                if (whi) atomicOr(&flagsm[wslot * 16 + 2 * wn + 1], 1u);
            }
            __syncthreads();
        } else {
            // final: a10 = soft(v10) -> out
#pragma unroll
            for (int fm = 0; fm < 2; fm++)
#pragma unroll
            for (int rh = 0; rh < 2; rh++) {
                int rl = m0 + fm * 16 + rh * 8 + r4;
                float* orow = out + (size_t)(grow0 + rl) * DIMN;
#pragma unroll
                for (int ni = 0; ni < 8; ni++) {
                    float v0 = acc[fm][ni][rh * 2 + 0];
                    float v1 = acc[fm][ni][rh * 2 + 1];
                    float s0 = fabsf(v0) - lam, s1 = fabsf(v1) - lam;
                    float2 o;
                    o.x = (s0 > 0.0f) ? copysignf(s0, v0) : 0.0f;
                    o.y = (s1 > 0.0f) ? copysignf(s1, v1) : 0.0f;
                    *(float2*)(orow + n0 + ni * 8 + c2) = o;
                }
            }
        }
    }
}

extern "C" void kernel_launch(void* const* d_in, const int* in_sizes, int n_in,
                              void* d_out, int out_size) {
    const float* u = nullptr;
    const float* G = nullptr;
    const float* ll = nullptr;
    for (int i = 0; i < n_in; i++) {
        if (in_sizes[i] == NROWS * DIMN)      u  = (const float*)d_in[i];
        else if (in_sizes[i] == DIMN * DIMN)  G  = (const float*)d_in[i];
        else                                  ll = (const float*)d_in[i];
    }
    float* out = (float*)d_out;

    lca_prep_kernel<<<DIMN, DIMN>>>(G);

    cudaFuncSetAttribute(lca_main_kernel,
                         cudaFuncAttributeMaxDynamicSharedMemorySize, SMEM_TOTAL);
    lca_main_kernel<<<NCTAS, NTHREADS, SMEM_TOTAL>>>(u, ll, out);
}

// round 4
// speedup vs baseline: 1.0934x; 1.0934x over previous
#include <cuda_runtime.h>
#include <cuda_bf16.h>
#include <cstdint>

#define DIMN 512
#define MT   64
#define NROWS 65536
#define NCTAS (NROWS / MT)        // 1024
#define NTHREADS 512
#define ETA   0.1f
#define OMETA 0.9f

// smem: a-tile [64][512] bf16 swizzled (64KB) + 2 G chunk buffers [64][512] bf16 (64KB each) + flags
static constexpr uint32_t A_OFF   = 0;
static constexpr uint32_t G_OFF0  = 65536;
static constexpr uint32_t G_OFF1  = 131072;
static constexpr uint32_t FL_OFF  = 196608;       // flags[2][8] uint32 = 64B
static constexpr uint32_t SMEM_TOTAL = 196672;

#define NCH_TOTAL (9 * 8)         // 72 chunks of 64 rows

// G' = -eta * (0.5*(G+G^T)) with zero diagonal, bf16, row-major [K=512][N=512]
__device__ __nv_bfloat16 g_gp[DIMN * DIMN];

__global__ void lca_prep_kernel(const float* __restrict__ G) {
    int idx = blockIdx.x * blockDim.x + threadIdx.x;
    int i = idx >> 9, j = idx & 511;
    float v = (i == j) ? 0.0f : -ETA * 0.5f * (G[idx] + G[j * DIMN + i]);
    g_gp[idx] = __float2bfloat16(v);
}

__device__ __forceinline__ uint32_t smem_u32(const void* p) {
    uint32_t a;
    asm("{ .reg .u64 t; cvta.to.shared.u64 t, %1; cvt.u32.u64 %0, t; }" : "=r"(a) : "l"(p));
    return a;
}
__device__ __forceinline__ void ldsm4(uint32_t* r, uint32_t addr) {
    asm volatile("ldmatrix.sync.aligned.m8n8.x4.shared.b16 {%0,%1,%2,%3}, [%4];"
                 : "=r"(r[0]), "=r"(r[1]), "=r"(r[2]), "=r"(r[3]) : "r"(addr));
}
__device__ __forceinline__ void ldsm4t(uint32_t* r, uint32_t addr) {
    asm volatile("ldmatrix.sync.aligned.m8n8.x4.trans.shared.b16 {%0,%1,%2,%3}, [%4];"
                 : "=r"(r[0]), "=r"(r[1]), "=r"(r[2]), "=r"(r[3]) : "r"(addr));
}
__device__ __forceinline__ void mma_bf16(float* c, const uint32_t* a, uint32_t b0, uint32_t b1) {
    asm volatile("mma.sync.aligned.m16n8k16.row.col.f32.bf16.bf16.f32 "
                 "{%0,%1,%2,%3}, {%4,%5,%6,%7}, {%8,%9}, {%0,%1,%2,%3};"
                 : "+f"(c[0]), "+f"(c[1]), "+f"(c[2]), "+f"(c[3])
                 : "r"(a[0]), "r"(a[1]), "r"(a[2]), "r"(a[3]), "r"(b0), "r"(b1));
}
__device__ __forceinline__ void cp_async16(uint32_t dst, const void* src) {
    asm volatile("cp.async.cg.shared.global [%0], [%1], 16;" :: "r"(dst), "l"(src) : "memory");
}

// load G chunk rb (64 rows, 64KB) into SMEM buffer boff; 4096 16B units, 8 per thread
__device__ __forceinline__ void load_chunk64(uint32_t sb, uint32_t boff, int rb, int tid) {
    const char* src = (const char*)g_gp + (size_t)rb * 65536 + (size_t)tid * 16;
#pragma unroll
    for (int j = 0; j < 8; j++) {
        int q = tid + j * 512;
        int r = q >> 6, cu = q & 63;
        uint32_t dst = sb + boff + (uint32_t)r * 1024u + ((uint32_t)(cu ^ (r & 7)) << 4);
        cp_async16(dst, src + j * 8192);
    }
    asm volatile("cp.async.commit_group;" ::: "memory");
}

__global__ __launch_bounds__(NTHREADS, 1)
void lca_main_kernel(const float* __restrict__ u,
                     const float* __restrict__ log_lam,
                     float* __restrict__ out) {
    extern __shared__ char smem[];
    const uint32_t sb = smem_u32(smem);
    uint32_t* flagsm = reinterpret_cast<uint32_t*>(smem + FL_OFF);   // [2][8]
    const int tid  = threadIdx.x;
    const int lane = tid & 31;
    const int warp = tid >> 5;
    const int wm = warp >> 3;              // 0..1
    const int wn = warp & 7;               // 0..7
    const int m0 = wm * 32;
    const int n0 = wn * 64;
    const uint32_t un0 = (uint32_t)(n0 >> 3);
    const int grow0 = blockIdx.x * MT;
    const float lam = expf(log_lam[0]);
    const int r4 = lane >> 2;
    const int c2 = (lane & 3) * 2;

    float acc[2][8][4];

    const uint32_t a_lrow0 = sb + A_OFF + (uint32_t)(m0 + (lane & 15)) * 1024u;
    const uint32_t a_lrow1 = a_lrow0 + 16u * 1024u;
    const uint32_t a_cbs = ((uint32_t)(lane >> 4)) ^ ((uint32_t)(lane & 7));
    const uint32_t b_rowoff = (uint32_t)(lane & 15) * 1024u;
    uint32_t b_pu[4];
#pragma unroll
    for (int p = 0; p < 4; p++)
        b_pu[p] = (((un0 + (uint32_t)(2 * p) + (uint32_t)(lane >> 4)) ^ (uint32_t)(lane & 7)) << 4);

    if (tid < 16) flagsm[tid] = 0u;
    load_chunk64(sb, G_OFF0, 0, tid);     // chunk 0 -> buf0 (overlaps init epilogue)

    // ---- init: v1 = eta*u; a1 = soft(v1) -> SMEM + flags slot0; acc = 0.9*v1 + 0.1*u ----
    {
        bool nzw = false;
#pragma unroll
        for (int fm = 0; fm < 2; fm++)
#pragma unroll
        for (int rh = 0; rh < 2; rh++) {
            int rl = m0 + fm * 16 + rh * 8 + r4;
            const float* urow = u + (size_t)(grow0 + rl) * DIMN;
            uint32_t abase = sb + A_OFF + (uint32_t)rl * 1024u + (uint32_t)(c2 * 2);
            uint32_t sw = (uint32_t)(rl & 7);
#pragma unroll
            for (int ni = 0; ni < 8; ni++) {
                float2 uv = *(const float2*)(urow + n0 + ni * 8 + c2);
                float v0 = ETA * uv.x, v1 = ETA * uv.y;
                float s0 = fabsf(v0) - lam, s1 = fabsf(v1) - lam;
                float a0 = (s0 > 0.0f) ? copysignf(s0, v0) : 0.0f;
                float a1 = (s1 > 0.0f) ? copysignf(s1, v1) : 0.0f;
                nzw |= (a0 != 0.0f) || (a1 != 0.0f);
                __nv_bfloat162 h2 = __floats2bfloat162_rn(a0, a1);
                uint32_t aaddr = abase + (((un0 + (uint32_t)ni) ^ sw) << 4);
                asm volatile("st.shared.b32 [%0], %1;" :: "r"(aaddr), "r"(*(uint32_t*)&h2) : "memory");
                acc[fm][ni][rh * 2 + 0] = fmaf(OMETA, v0, ETA * uv.x);
                acc[fm][ni][rh * 2 + 1] = fmaf(OMETA, v1, ETA * uv.y);
            }
        }
        if (__any_sync(0xFFFFFFFFu, nzw) && lane == 0) atomicOr(&flagsm[wn], 1u);
    }
    asm volatile("cp.async.wait_group 0;" ::: "memory");
    __syncthreads();    // chunk0 visible, flags slot0 ready

    // ---- 9 fused iterations, 8 chunks of 64 G-rows each ----
#pragma unroll 1
    for (int it = 0; it < 9; it++) {
        const int slot = it & 1;
#pragma unroll 1
        for (int kb = 0; kb < 8; kb++) {
            const int c = it * 8 + kb;
            const uint32_t buf = sb + ((c & 1) ? G_OFF1 : G_OFF0);
            // prefetch next chunk into other buffer (its data consumed only after next barrier)
            if (c + 1 < NCH_TOTAL)
                load_chunk64(sb, ((c & 1) ? G_OFF0 : G_OFF1), (kb + 1) & 7, tid);

            if (flagsm[slot * 8 + kb]) {
                uint32_t Af[2][8], Bf[2][16];
                // preload step 0
                {
                    uint32_t aoff = (((uint32_t)(kb << 3) ^ a_cbs) << 4);
                    ldsm4(&Af[0][0], a_lrow0 + aoff);
                    ldsm4(&Af[0][4], a_lrow1 + aoff);
                    uint32_t brow = buf + b_rowoff;
#pragma unroll
                    for (int p = 0; p < 4; p++) ldsm4t(&Bf[0][4 * p], brow + b_pu[p]);
                }
#pragma unroll
                for (int h = 0; h < 4; h++) {
                    const int cur = h & 1, nxt = cur ^ 1;
                    if (h < 3) {
                        uint32_t aoff = (((uint32_t)((kb * 4 + h + 1) << 1) ^ a_cbs) << 4);
                        ldsm4(&Af[nxt][0], a_lrow0 + aoff);
                        ldsm4(&Af[nxt][4], a_lrow1 + aoff);
                        uint32_t brow = buf + b_rowoff + (uint32_t)((h + 1) * 16384);
#pragma unroll
                        for (int p = 0; p < 4; p++) ldsm4t(&Bf[nxt][4 * p], brow + b_pu[p]);
                    }
#pragma unroll
                    for (int p = 0; p < 4; p++) {
                        mma_bf16(acc[0][2 * p + 0], &Af[cur][0], Bf[cur][4 * p + 0], Bf[cur][4 * p + 1]);
                        mma_bf16(acc[0][2 * p + 1], &Af[cur][0], Bf[cur][4 * p + 2], Bf[cur][4 * p + 3]);
                        mma_bf16(acc[1][2 * p + 0], &Af[cur][4], Bf[cur][4 * p + 0], Bf[cur][4 * p + 1]);
                        mma_bf16(acc[1][2 * p + 1], &Af[cur][4], Bf[cur][4 * p + 2], Bf[cur][4 * p + 3]);
                    }
                }
            }
            asm volatile("cp.async.wait_group 0;" ::: "memory");
            __syncthreads();   // next chunk visible; all warps done with this chunk & A-tile
            if (kb == 0 && tid < 8) flagsm[((it + 1) & 1) * 8 + tid] = 0u;
        }

        if (it < 8) {
            bool nzw = false;
            const int wslot = (it + 1) & 1;
#pragma unroll
            for (int fm = 0; fm < 2; fm++)
#pragma unroll
            for (int rh = 0; rh < 2; rh++) {
                int rl = m0 + fm * 16 + rh * 8 + r4;
                const float* urow = u + (size_t)(grow0 + rl) * DIMN;
                uint32_t abase = sb + A_OFF + (uint32_t)rl * 1024u + (uint32_t)(c2 * 2);
                uint32_t sw = (uint32_t)(rl & 7);
#pragma unroll
                for (int ni = 0; ni < 8; ni++) {
                    float v0 = acc[fm][ni][rh * 2 + 0];
                    float v1 = acc[fm][ni][rh * 2 + 1];
                    float s0 = fabsf(v0) - lam, s1 = fabsf(v1) - lam;
                    float a0 = (s0 > 0.0f) ? copysignf(s0, v0) : 0.0f;
                    float a1 = (s1 > 0.0f) ? copysignf(s1, v1) : 0.0f;
                    nzw |= (a0 != 0.0f) || (a1 != 0.0f);
                    __nv_bfloat162 h2 = __floats2bfloat162_rn(a0, a1);
                    uint32_t aaddr = abase + (((un0 + (uint32_t)ni) ^ sw) << 4);
                    asm volatile("st.shared.b32 [%0], %1;" :: "r"(aaddr), "r"(*(uint32_t*)&h2) : "memory");
                    float2 uv = *(const float2*)(urow + n0 + ni * 8 + c2);
                    acc[fm][ni][rh * 2 + 0] = fmaf(OMETA, v0, ETA * uv.x);
                    acc[fm][ni][rh * 2 + 1] = fmaf(OMETA, v1, ETA * uv.y);
                }
            }
            if (__any_sync(0xFFFFFFFFu, nzw) && lane == 0)
                atomicOr(&flagsm[wslot * 8 + wn], 1u);
            __syncthreads();
        } else {
            // final: a10 = soft(v10) -> out
#pragma unroll
            for (int fm = 0; fm < 2; fm++)
#pragma unroll
            for (int rh = 0; rh < 2; rh++) {
                int rl = m0 + fm * 16 + rh * 8 + r4;
                float* orow = out + (size_t)(grow0 + rl) * DIMN;
#pragma unroll
                for (int ni = 0; ni < 8; ni++) {
                    float v0 = acc[fm][ni][rh * 2 + 0];
                    float v1 = acc[fm][ni][rh * 2 + 1];
                    float s0 = fabsf(v0) - lam, s1 = fabsf(v1) - lam;
                    float2 o;
                    o.x = (s0 > 0.0f) ? copysignf(s0, v0) : 0.0f;
                    o.y = (s1 > 0.0f) ? copysignf(s1, v1) : 0.0f;
                    *(float2*)(orow + n0 + ni * 8 + c2) = o;
                }
            }
        }
    }
}

extern "C" void kernel_launch(void* const* d_in, const int* in_sizes, int n_in,
                              void* d_out, int out_size) {
    const float* u = nullptr;
    const float* G = nullptr;
    const float* ll = nullptr;
    for (int i = 0; i < n_in; i++) {
        if (in_sizes[i] == NROWS * DIMN)      u  = (const float*)d_in[i];
        else if (in_sizes[i] == DIMN * DIMN)  G  = (const float*)d_in[i];
        else                                  ll = (const float*)d_in[i];
    }
    float* out = (float*)d_out;

    lca_prep_kernel<<<DIMN, DIMN>>>(G);

    cudaFuncSetAttribute(lca_main_kernel,
                         cudaFuncAttributeMaxDynamicSharedMemorySize, SMEM_TOTAL);
    lca_main_kernel<<<NCTAS, NTHREADS, SMEM_TOTAL>>>(u, ll, out);
}